// round 2
// baseline (speedup 1.0000x reference)
#include <cuda_runtime.h>
#include <math.h>

// Problem constants (MoEFeedForward_42554535969109): B=4, L=2048 -> N=8192
#define NTOK 8192
#define DDIM 1024
#define HDIM 2048
#define NEXP 8
#define NSH 2
#define MAXP (2 * NTOK)            // token-expert pairs (top-2)
#define MAXP_PAD (MAXP + NEXP*128) // per-expert segments padded to 128
#define TILES_MAX (MAXP_PAD / 128) // 136

// ------------------------- scratch (__device__ globals) -------------------------
__device__ float g_h_routed[(size_t)MAXP_PAD * HDIM]; // gelu(x@w1+b1) per pair slot
__device__ float g_ybuf[(size_t)MAXP_PAD * DDIM];     // (h@w2+b2) per pair slot
__device__ float g_hs[(size_t)NSH * NTOK * HDIM];     // shared hidden
__device__ float g_ys[(size_t)NSH * NTOK * DDIM];     // shared out per s
__device__ int   g_pair_token[MAXP_PAD];              // slot -> token (-1 pad)
__device__ int   g_slot_of[MAXP];                     // (n,k) -> slot
__device__ float g_gate[MAXP];                        // (n,k) -> softmax weight
__device__ int   g_topi[MAXP];                        // (n,k) -> expert id
__device__ int   g_tile_expert[TILES_MAX];            // m-tile -> expert (-1 unused)

// ------------------------- router: gates, top-2, softmax -------------------------
__global__ void router_kernel(const float* __restrict__ x,
                              const float* __restrict__ rw,
                              const float* __restrict__ rb, int N) {
    int w = (blockIdx.x * blockDim.x + threadIdx.x) >> 5;
    int lane = threadIdx.x & 31;
    if (w >= N) return;
    const float* xr = x + (size_t)w * DDIM;
    float acc[NEXP];
#pragma unroll
    for (int e = 0; e < NEXP; e++) acc[e] = 0.f;
    for (int d = lane; d < DDIM; d += 32) {
        float xv = xr[d];
        const float* r = rw + (size_t)d * NEXP;
#pragma unroll
        for (int e = 0; e < NEXP; e++) acc[e] = fmaf(xv, r[e], acc[e]);
    }
#pragma unroll
    for (int e = 0; e < NEXP; e++)
        for (int o = 16; o > 0; o >>= 1)
            acc[e] += __shfl_xor_sync(0xffffffffu, acc[e], o);
    if (lane == 0) {
        float v0 = -1e30f, v1 = -1e30f;
        int i0 = 0, i1 = 0;
#pragma unroll
        for (int e = 0; e < NEXP; e++) {
            float v = acc[e] + rb[e];
            if (v > v0) { v1 = v0; i1 = i0; v0 = v; i0 = e; }
            else if (v > v1) { v1 = v; i1 = e; }
        }
        float p1 = expf(v1 - v0);
        float inv = 1.0f / (1.0f + p1);
        g_topi[2 * w] = i0;     g_topi[2 * w + 1] = i1;
        g_gate[2 * w] = inv;    g_gate[2 * w + 1] = p1 * inv;
    }
}

// ------------------------- bucketing: padded per-expert segments -------------------------
__global__ void bucket_kernel(int N) {
    __shared__ int s_cnt[NEXP];
    __shared__ int s_off[NEXP + 1];
    __shared__ int s_c2[NEXP];
    int tid = threadIdx.x;
    if (tid < NEXP) { s_cnt[tid] = 0; s_c2[tid] = 0; }
    __syncthreads();
    int P = 2 * N;
    for (int p = tid; p < P; p += blockDim.x) atomicAdd(&s_cnt[g_topi[p]], 1);
    for (int i = tid; i < MAXP_PAD; i += blockDim.x) g_pair_token[i] = -1;
    __syncthreads();
    if (tid == 0) {
        int o = 0;
        for (int e = 0; e < NEXP; e++) { s_off[e] = o; o += ((s_cnt[e] + 127) >> 7) << 7; }
        s_off[NEXP] = o;
        int total = o >> 7;
        for (int t = 0; t < TILES_MAX; t++) {
            int ex = -1;
            if (t < total) {
                int s = t << 7;
                for (int e = 0; e < NEXP; e++)
                    if (s >= s_off[e] && s < s_off[e + 1]) ex = e;
            }
            g_tile_expert[t] = ex;
        }
    }
    __syncthreads();
    for (int p = tid; p < P; p += blockDim.x) {
        int e = g_topi[p];
        int pos = atomicAdd(&s_c2[e], 1);
        int slot = s_off[e] + pos;
        g_pair_token[slot] = p >> 1;
        g_slot_of[p] = slot;
    }
}

// ------------------------- tiled fp32 GEMM: C = act(A @ W[e] + bias[e]) -------------------------
// BM=BN=128, BK=8, 256 threads, 8x8 per thread, register-staged double buffer.
template <bool GELU>
__global__ void __launch_bounds__(256, 2)
gemm_kernel(const float* __restrict__ A_base, long long a_z_stride,
            const float* __restrict__ W_base, long long w_stride,
            const float* __restrict__ bias_base, int bias_stride,
            float* __restrict__ C_base, long long c_z_stride,
            const int* __restrict__ row_gather,   // null -> row = global row
            const int* __restrict__ tile_expert,  // null -> expert = blockIdx.z
            int Kdim, int Ndim) {
    constexpr int BM = 128, BN = 128, BK = 8, TM = 8, TN = 8;
    int tileM = blockIdx.x, tileN = blockIdx.y, z = blockIdx.z;
    int expert = tile_expert ? tile_expert[tileM] : z;
    if (expert < 0) return;

    const float* A = A_base + a_z_stride * z;
    float* C = C_base + c_z_stride * z;
    const float* W = W_base + w_stride * expert;
    const float* bias = bias_base + (long long)bias_stride * expert + tileN * BN;

    __shared__ float As[BK][BM];
    __shared__ float Bs[BK][BN];

    int tid = threadIdx.x;
    int ty = tid >> 4, tx = tid & 15;
    int aRow = tid >> 1, aCol = (tid & 1) * 4;
    int bRow = tid >> 5, bCol = (tid & 31) * 4;

    int mBase = tileM * BM;
    int srcRow = row_gather ? row_gather[mBase + aRow] : (mBase + aRow);
    const float* aPtr = (srcRow >= 0) ? (A + (size_t)srcRow * Kdim + aCol) : nullptr;
    const float* bPtr = W + (size_t)bRow * Ndim + (size_t)tileN * BN + bCol;

    float acc[TM][TN];
#pragma unroll
    for (int i = 0; i < TM; i++)
#pragma unroll
        for (int j = 0; j < TN; j++) acc[i][j] = 0.f;

    float4 aReg = aPtr ? *(const float4*)aPtr : make_float4(0.f, 0.f, 0.f, 0.f);
    float4 bReg = *(const float4*)bPtr;

    for (int k0 = 0; k0 < Kdim; k0 += BK) {
        As[aCol + 0][aRow] = aReg.x;
        As[aCol + 1][aRow] = aReg.y;
        As[aCol + 2][aRow] = aReg.z;
        As[aCol + 3][aRow] = aReg.w;
        *(float4*)&Bs[bRow][bCol] = bReg;
        __syncthreads();
        int kn = k0 + BK;
        if (kn < Kdim) {
            aReg = aPtr ? *(const float4*)(aPtr + kn) : make_float4(0.f, 0.f, 0.f, 0.f);
            bReg = *(const float4*)(bPtr + (size_t)kn * Ndim);
        }
#pragma unroll
        for (int kk = 0; kk < BK; kk++) {
            float a[TM], b[TN];
            *(float4*)&a[0] = *(const float4*)&As[kk][ty * TM];
            *(float4*)&a[4] = *(const float4*)&As[kk][ty * TM + 4];
            *(float4*)&b[0] = *(const float4*)&Bs[kk][tx * TN];
            *(float4*)&b[4] = *(const float4*)&Bs[kk][tx * TN + 4];
#pragma unroll
            for (int i = 0; i < TM; i++)
#pragma unroll
                for (int j = 0; j < TN; j++)
                    acc[i][j] = fmaf(a[i], b[j], acc[i][j]);
        }
        __syncthreads();
    }

    // epilogue
#pragma unroll
    for (int i = 0; i < TM; i++) {
        size_t r = (size_t)mBase + ty * TM + i;
        float* crow = C + r * (size_t)Ndim + (size_t)tileN * BN + tx * TN;
        float v[TN];
#pragma unroll
        for (int j = 0; j < TN; j++) {
            float t = acc[i][j] + bias[tx * TN + j];
            if (GELU) t = 0.5f * t * (1.0f + erff(t * 0.70710678118654752f));
            v[j] = t;
        }
        *(float4*)&crow[0] = *(float4*)&v[0];
        *(float4*)&crow[4] = *(float4*)&v[4];
    }
}

// ------------------------- final combine -------------------------
__global__ void combine_kernel(float* __restrict__ out, int N) {
    int idx = blockIdx.x * blockDim.x + threadIdx.x;
    int total = N * (DDIM / 4);
    if (idx >= total) return;
    int n = idx / (DDIM / 4);
    int d = (idx % (DDIM / 4)) * 4;
    const float4 s0 = *(const float4*)&g_ys[(size_t)n * DDIM + d];
    const float4 s1 = *(const float4*)&g_ys[(size_t)N * DDIM + (size_t)n * DDIM + d];
    int sl0 = g_slot_of[2 * n], sl1 = g_slot_of[2 * n + 1];
    float w0 = g_gate[2 * n], w1 = g_gate[2 * n + 1];
    const float4 y0 = *(const float4*)&g_ybuf[(size_t)sl0 * DDIM + d];
    const float4 y1 = *(const float4*)&g_ybuf[(size_t)sl1 * DDIM + d];
    const float inv_s = 1.0f / NSH;
    float4 o;
    o.x = inv_s * (s0.x + s1.x) + w0 * y0.x + w1 * y1.x;
    o.y = inv_s * (s0.y + s1.y) + w0 * y0.y + w1 * y1.y;
    o.z = inv_s * (s0.z + s1.z) + w0 * y0.z + w1 * y1.z;
    o.w = inv_s * (s0.w + s1.w) + w0 * y0.w + w1 * y1.w;
    *(float4*)&out[(size_t)n * DDIM + d] = o;
}

// ------------------------- launch -------------------------
extern "C" void kernel_launch(void* const* d_in, const int* in_sizes, int n_in,
                              void* d_out, int out_size) {
    const float* x   = (const float*)d_in[0];
    const float* rw  = (const float*)d_in[1];
    const float* rb  = (const float*)d_in[2];
    const float* w1  = (const float*)d_in[3];
    const float* b1  = (const float*)d_in[4];
    const float* w2  = (const float*)d_in[5];
    const float* b2  = (const float*)d_in[6];
    const float* sw1 = (const float*)d_in[7];
    const float* sb1 = (const float*)d_in[8];
    const float* sw2 = (const float*)d_in[9];
    const float* sb2 = (const float*)d_in[10];
    float* out = (float*)d_out;
    int N = in_sizes[0] / DDIM;

    void *p_hr, *p_yb, *p_hs, *p_ys, *p_pt, *p_te;
    cudaGetSymbolAddress(&p_hr, g_h_routed);
    cudaGetSymbolAddress(&p_yb, g_ybuf);
    cudaGetSymbolAddress(&p_hs, g_hs);
    cudaGetSymbolAddress(&p_ys, g_ys);
    cudaGetSymbolAddress(&p_pt, g_pair_token);
    cudaGetSymbolAddress(&p_te, g_tile_expert);

    // 1) router
    router_kernel<<<(N + 7) / 8, 256>>>(x, rw, rb, N);
    // 2) bucketing
    bucket_kernel<<<1, 256>>>(N);
    // 3) routed GEMM1: h = gelu(x[gather] @ w1[e] + b1[e])
    gemm_kernel<true><<<dim3(TILES_MAX, HDIM / 128, 1), 256>>>(
        x, 0, w1, (long long)DDIM * HDIM, b1, HDIM,
        (float*)p_hr, 0, (const int*)p_pt, (const int*)p_te, DDIM, HDIM);
    // 4) routed GEMM2: y = h @ w2[e] + b2[e]
    gemm_kernel<false><<<dim3(TILES_MAX, DDIM / 128, 1), 256>>>(
        (const float*)p_hr, 0, w2, (long long)HDIM * DDIM, b2, DDIM,
        (float*)p_yb, 0, nullptr, (const int*)p_te, HDIM, DDIM);
    // 5) shared GEMM1: hs[s] = gelu(x @ sw1[s] + sb1[s])
    gemm_kernel<true><<<dim3(N / 128, HDIM / 128, NSH), 256>>>(
        x, 0, sw1, (long long)DDIM * HDIM, sb1, HDIM,
        (float*)p_hs, (long long)N * HDIM, nullptr, nullptr, DDIM, HDIM);
    // 6) shared GEMM2: ys[s] = hs[s] @ sw2[s] + sb2[s]
    gemm_kernel<false><<<dim3(N / 128, DDIM / 128, NSH), 256>>>(
        (const float*)p_hs, (long long)N * HDIM, sw2, (long long)HDIM * DDIM, sb2, DDIM,
        (float*)p_ys, (long long)N * DDIM, nullptr, nullptr, HDIM, DDIM);
    // 7) combine
    combine_kernel<<<(N * (DDIM / 4) + 255) / 256, 256>>>(out, N);
}

// round 7
// speedup vs baseline: 1.9974x; 1.9974x over previous
#include <cuda_runtime.h>
#include <cuda_bf16.h>
#include <math.h>

// Problem constants (MoEFeedForward_42554535969109): B=4, L=2048 -> N=8192
#define NTOK 8192
#define DDIM 1024
#define HDIM 2048
#define NEXP 8
#define NSH 2
#define MAXP (2 * NTOK)            // token-expert pairs (top-2)
#define MAXP_PAD (MAXP + NEXP*128) // per-expert segments padded to 128
#define TILES_MAX (MAXP_PAD / 128) // 136

// ------------------------- scratch (__device__ globals) -------------------------
__device__ float g_h_routed[(size_t)MAXP_PAD * HDIM]; // gelu(x@w1+b1) per pair slot
__device__ float g_ybuf[(size_t)MAXP_PAD * DDIM];     // (h@w2+b2) per pair slot
__device__ float g_hs[(size_t)NSH * NTOK * HDIM];     // shared hidden
__device__ float g_ys[(size_t)NSH * NTOK * DDIM];     // shared out per s
__device__ int   g_pair_token[MAXP_PAD];              // slot -> token (-1 pad)
__device__ int   g_slot_of[MAXP];                     // (n,k) -> slot
__device__ float g_gate[MAXP];                        // (n,k) -> softmax weight
__device__ int   g_topi[MAXP];                        // (n,k) -> expert id
__device__ int   g_tile_expert[TILES_MAX];            // m-tile -> expert (-1 unused)

// ------------------------- router: gates, top-2, softmax -------------------------
__global__ void router_kernel(const float* __restrict__ x,
                              const float* __restrict__ rw,
                              const float* __restrict__ rb, int N) {
    int w = (blockIdx.x * blockDim.x + threadIdx.x) >> 5;
    int lane = threadIdx.x & 31;
    if (w >= N) return;
    const float* xr = x + (size_t)w * DDIM;
    float acc[NEXP];
#pragma unroll
    for (int e = 0; e < NEXP; e++) acc[e] = 0.f;
    for (int d = lane; d < DDIM; d += 32) {
        float xv = xr[d];
        const float* r = rw + (size_t)d * NEXP;
#pragma unroll
        for (int e = 0; e < NEXP; e++) acc[e] = fmaf(xv, r[e], acc[e]);
    }
#pragma unroll
    for (int e = 0; e < NEXP; e++)
        for (int o = 16; o > 0; o >>= 1)
            acc[e] += __shfl_xor_sync(0xffffffffu, acc[e], o);
    if (lane == 0) {
        float v0 = -1e30f, v1 = -1e30f;
        int i0 = 0, i1 = 0;
#pragma unroll
        for (int e = 0; e < NEXP; e++) {
            float v = acc[e] + rb[e];
            if (v > v0) { v1 = v0; i1 = i0; v0 = v; i0 = e; }
            else if (v > v1) { v1 = v; i1 = e; }
        }
        float p1 = expf(v1 - v0);
        float inv = 1.0f / (1.0f + p1);
        g_topi[2 * w] = i0;     g_topi[2 * w + 1] = i1;
        g_gate[2 * w] = inv;    g_gate[2 * w + 1] = p1 * inv;
    }
}

// ------------------------- bucketing: padded per-expert segments -------------------------
__global__ void bucket_kernel(int N) {
    __shared__ int s_cnt[NEXP];
    __shared__ int s_off[NEXP + 1];
    __shared__ int s_c2[NEXP];
    int tid = threadIdx.x;
    if (tid < NEXP) { s_cnt[tid] = 0; s_c2[tid] = 0; }
    __syncthreads();
    int P = 2 * N;
    for (int p = tid; p < P; p += blockDim.x) atomicAdd(&s_cnt[g_topi[p]], 1);
    for (int i = tid; i < MAXP_PAD; i += blockDim.x) g_pair_token[i] = -1;
    __syncthreads();
    if (tid == 0) {
        int o = 0;
        for (int e = 0; e < NEXP; e++) { s_off[e] = o; o += ((s_cnt[e] + 127) >> 7) << 7; }
        s_off[NEXP] = o;
        int total = o >> 7;
        for (int t = 0; t < TILES_MAX; t++) {
            int ex = -1;
            if (t < total) {
                int s = t << 7;
                for (int e = 0; e < NEXP; e++)
                    if (s >= s_off[e] && s < s_off[e + 1]) ex = e;
            }
            g_tile_expert[t] = ex;
        }
    }
    __syncthreads();
    for (int p = tid; p < P; p += blockDim.x) {
        int e = g_topi[p];
        int pos = atomicAdd(&s_c2[e], 1);
        int slot = s_off[e] + pos;
        g_pair_token[slot] = p >> 1;
        g_slot_of[p] = slot;
    }
}

// ------------------------- bf16x3 split helpers -------------------------
__device__ __forceinline__ void cvt_pair(float x0, float x1,
                                         unsigned& hi, unsigned& lo) {
    __nv_bfloat16 h0 = __float2bfloat16(x0);
    __nv_bfloat16 h1 = __float2bfloat16(x1);
    float r0 = x0 - __bfloat162float(h0);
    float r1 = x1 - __bfloat162float(h1);
    __nv_bfloat16 l0 = __float2bfloat16(r0);
    __nv_bfloat16 l1 = __float2bfloat16(r1);
    hi = (unsigned)__bfloat16_as_ushort(h0) |
         ((unsigned)__bfloat16_as_ushort(h1) << 16);
    lo = (unsigned)__bfloat16_as_ushort(l0) |
         ((unsigned)__bfloat16_as_ushort(l1) << 16);
}

#define MMA_BF16(accp, a, b)                                                  \
    asm volatile(                                                             \
        "mma.sync.aligned.m16n8k16.row.col.f32.bf16.bf16.f32 "                \
        "{%0,%1,%2,%3},{%4,%5,%6,%7},{%8,%9},{%0,%1,%2,%3};"                  \
        : "+f"((accp)[0]), "+f"((accp)[1]), "+f"((accp)[2]), "+f"((accp)[3])  \
        : "r"((a)[0]), "r"((a)[1]), "r"((a)[2]), "r"((a)[3]),                 \
          "r"((b)[0]), "r"((b)[1]))

// ------------------------- tensor-core GEMM: C = act(A @ W[e] + bias[e]) -------------------------
// BM=BN=128, BK=32. 256 threads = 8 warps, each warp computes 64x32 of C.
// fp32 inputs split into bf16 hi/lo (bf16x3 scheme: HH + HL + LH).
// Shared layout: b32 k-pair words, [kpair][M or N] with stride 136 b32 so the
// 4 fragment pair-rows hit bank offsets {0,8,16,24} -> conflict-free LDS.
#define SMS 136
template <bool GELU>
__global__ void __launch_bounds__(256, 1)
mma_gemm(const float* __restrict__ A_base, long long a_z_stride,
         const float* __restrict__ W_base, long long w_stride,
         const float* __restrict__ bias_base, int bias_stride,
         float* __restrict__ C_base, long long c_z_stride,
         const int* __restrict__ row_gather,   // null -> row = global row
         const int* __restrict__ tile_expert,  // null -> expert = blockIdx.z
         int Kdim, int Ndim) {
    int tileM = blockIdx.x, tileN = blockIdx.y, z = blockIdx.z;
    int expert = tile_expert ? tile_expert[tileM] : z;
    if (expert < 0) return;

    const float* A = A_base + a_z_stride * z;
    float* C = C_base + c_z_stride * z;
    const float* W = W_base + w_stride * expert + (size_t)tileN * 128;
    const float* bias = bias_base + (long long)bias_stride * expert + tileN * 128;

    __shared__ unsigned As_hi[16][SMS];
    __shared__ unsigned As_lo[16][SMS];
    __shared__ unsigned Bs_hi[16][SMS];
    __shared__ unsigned Bs_lo[16][SMS];

    int tid = threadIdx.x;
    int lane = tid & 31, wid = tid >> 5;
    int wm = (wid >> 2) * 64;   // warp M offset (0 or 64)
    int wn = (wid & 3) * 32;    // warp N offset (0,32,64,96)

    // A loader: kp_a = k-pair index 0..15, mr = row group
    int kp_a = tid & 15, mr = tid >> 4;
    // B loader: n2 = col pair, kq = base k-pair
    int n2 = (tid & 63) * 2, kq = tid >> 6;

    int mBase = tileM * 128;
    int srow[8];
#pragma unroll
    for (int i = 0; i < 8; i++) {
        int m = i * 16 + mr;
        srow[i] = row_gather ? row_gather[mBase + m] : (mBase + m);
    }

    float acc[4][4][4];
#pragma unroll
    for (int a = 0; a < 4; a++)
#pragma unroll
        for (int b = 0; b < 4; b++)
#pragma unroll
            for (int c = 0; c < 4; c++) acc[a][b][c] = 0.f;

    int nKb = Kdim >> 5;
    float2 apf[8], bpf0[4], bpf1[4];

    // prefetch k-block 0
#pragma unroll
    for (int i = 0; i < 8; i++)
        apf[i] = (srow[i] >= 0)
                     ? *(const float2*)(A + (size_t)srow[i] * Kdim + 2 * kp_a)
                     : make_float2(0.f, 0.f);
#pragma unroll
    for (int j = 0; j < 4; j++) {
        int kp = kq + 4 * j;
        bpf0[j] = *(const float2*)(W + (size_t)(2 * kp) * Ndim + n2);
        bpf1[j] = *(const float2*)(W + (size_t)(2 * kp + 1) * Ndim + n2);
    }

    for (int kb = 0; kb < nKb; kb++) {
        __syncthreads();
        // convert + store staged tile to shared
#pragma unroll
        for (int i = 0; i < 8; i++) {
            unsigned h, l;
            cvt_pair(apf[i].x, apf[i].y, h, l);
            As_hi[kp_a][i * 16 + mr] = h;
            As_lo[kp_a][i * 16 + mr] = l;
        }
#pragma unroll
        for (int j = 0; j < 4; j++) {
            int kp = kq + 4 * j;
            unsigned h, l;
            cvt_pair(bpf0[j].x, bpf1[j].x, h, l);
            Bs_hi[kp][n2] = h; Bs_lo[kp][n2] = l;
            cvt_pair(bpf0[j].y, bpf1[j].y, h, l);
            Bs_hi[kp][n2 + 1] = h; Bs_lo[kp][n2 + 1] = l;
        }
        __syncthreads();

        // prefetch next k-block (overlaps with mma below)
        if (kb + 1 < nKb) {
            int koff = (kb + 1) * 32;
#pragma unroll
            for (int i = 0; i < 8; i++)
                apf[i] = (srow[i] >= 0)
                             ? *(const float2*)(A + (size_t)srow[i] * Kdim + koff + 2 * kp_a)
                             : make_float2(0.f, 0.f);
#pragma unroll
            for (int j = 0; j < 4; j++) {
                int kp = kq + 4 * j;
                bpf0[j] = *(const float2*)(W + (size_t)(koff + 2 * kp) * Ndim + n2);
                bpf1[j] = *(const float2*)(W + (size_t)(koff + 2 * kp + 1) * Ndim + n2);
            }
        }

        // two k16 steps per k-block
#pragma unroll
        for (int ks = 0; ks < 2; ks++) {
            int r = ks * 8 + (lane & 3);
            int cm = lane >> 2;
            unsigned ah[4][4], al[4][4], bh[4][2], bl[4][2];
#pragma unroll
            for (int mt = 0; mt < 4; mt++) {
                int m0 = wm + mt * 16 + cm;
                ah[mt][0] = As_hi[r][m0];     ah[mt][1] = As_hi[r][m0 + 8];
                ah[mt][2] = As_hi[r + 4][m0]; ah[mt][3] = As_hi[r + 4][m0 + 8];
                al[mt][0] = As_lo[r][m0];     al[mt][1] = As_lo[r][m0 + 8];
                al[mt][2] = As_lo[r + 4][m0]; al[mt][3] = As_lo[r + 4][m0 + 8];
            }
#pragma unroll
            for (int nt = 0; nt < 4; nt++) {
                int n0 = wn + nt * 8 + cm;
                bh[nt][0] = Bs_hi[r][n0]; bh[nt][1] = Bs_hi[r + 4][n0];
                bl[nt][0] = Bs_lo[r][n0]; bl[nt][1] = Bs_lo[r + 4][n0];
            }
#pragma unroll
            for (int mt = 0; mt < 4; mt++)
#pragma unroll
                for (int nt = 0; nt < 4; nt++)
                    MMA_BF16(acc[mt][nt], ah[mt], bh[nt]);
#pragma unroll
            for (int mt = 0; mt < 4; mt++)
#pragma unroll
                for (int nt = 0; nt < 4; nt++)
                    MMA_BF16(acc[mt][nt], ah[mt], bl[nt]);
#pragma unroll
            for (int mt = 0; mt < 4; mt++)
#pragma unroll
                for (int nt = 0; nt < 4; nt++)
                    MMA_BF16(acc[mt][nt], al[mt], bh[nt]);
        }
    }

    // epilogue: bias + optional gelu, fp32 stores
#pragma unroll
    for (int mt = 0; mt < 4; mt++) {
#pragma unroll
        for (int nt = 0; nt < 4; nt++) {
            int row0 = mBase + wm + mt * 16 + (lane >> 2);
            int col = wn + nt * 8 + (lane & 3) * 2;
            float b0 = bias[col], b1 = bias[col + 1];
            float v0 = acc[mt][nt][0] + b0;
            float v1 = acc[mt][nt][1] + b1;
            float v2 = acc[mt][nt][2] + b0;
            float v3 = acc[mt][nt][3] + b1;
            if (GELU) {
                v0 = 0.5f * v0 * (1.0f + erff(v0 * 0.70710678118654752f));
                v1 = 0.5f * v1 * (1.0f + erff(v1 * 0.70710678118654752f));
                v2 = 0.5f * v2 * (1.0f + erff(v2 * 0.70710678118654752f));
                v3 = 0.5f * v3 * (1.0f + erff(v3 * 0.70710678118654752f));
            }
            size_t base = (size_t)row0 * Ndim + (size_t)tileN * 128 + col;
            *(float2*)&C[base] = make_float2(v0, v1);
            *(float2*)&C[base + 8 * (size_t)Ndim] = make_float2(v2, v3);
        }
    }
}

// ------------------------- final combine -------------------------
__global__ void combine_kernel(float* __restrict__ out, int N) {
    int idx = blockIdx.x * blockDim.x + threadIdx.x;
    int total = N * (DDIM / 4);
    if (idx >= total) return;
    int n = idx / (DDIM / 4);
    int d = (idx % (DDIM / 4)) * 4;
    const float4 s0 = *(const float4*)&g_ys[(size_t)n * DDIM + d];
    const float4 s1 = *(const float4*)&g_ys[(size_t)N * DDIM + (size_t)n * DDIM + d];
    int sl0 = g_slot_of[2 * n], sl1 = g_slot_of[2 * n + 1];
    float w0 = g_gate[2 * n], w1 = g_gate[2 * n + 1];
    const float4 y0 = *(const float4*)&g_ybuf[(size_t)sl0 * DDIM + d];
    const float4 y1 = *(const float4*)&g_ybuf[(size_t)sl1 * DDIM + d];
    const float inv_s = 1.0f / NSH;
    float4 o;
    o.x = inv_s * (s0.x + s1.x) + w0 * y0.x + w1 * y1.x;
    o.y = inv_s * (s0.y + s1.y) + w0 * y0.y + w1 * y1.y;
    o.z = inv_s * (s0.z + s1.z) + w0 * y0.z + w1 * y1.z;
    o.w = inv_s * (s0.w + s1.w) + w0 * y0.w + w1 * y1.w;
    *(float4*)&out[(size_t)n * DDIM + d] = o;
}

// ------------------------- launch -------------------------
extern "C" void kernel_launch(void* const* d_in, const int* in_sizes, int n_in,
                              void* d_out, int out_size) {
    const float* x   = (const float*)d_in[0];
    const float* rw  = (const float*)d_in[1];
    const float* rb  = (const float*)d_in[2];
    const float* w1  = (const float*)d_in[3];
    const float* b1  = (const float*)d_in[4];
    const float* w2  = (const float*)d_in[5];
    const float* b2  = (const float*)d_in[6];
    const float* sw1 = (const float*)d_in[7];
    const float* sb1 = (const float*)d_in[8];
    const float* sw2 = (const float*)d_in[9];
    const float* sb2 = (const float*)d_in[10];
    float* out = (float*)d_out;
    int N = in_sizes[0] / DDIM;

    void *p_hr, *p_yb, *p_hs, *p_ys, *p_pt, *p_te;
    cudaGetSymbolAddress(&p_hr, g_h_routed);
    cudaGetSymbolAddress(&p_yb, g_ybuf);
    cudaGetSymbolAddress(&p_hs, g_hs);
    cudaGetSymbolAddress(&p_ys, g_ys);
    cudaGetSymbolAddress(&p_pt, g_pair_token);
    cudaGetSymbolAddress(&p_te, g_tile_expert);

    // 1) router
    router_kernel<<<(N + 7) / 8, 256>>>(x, rw, rb, N);
    // 2) bucketing
    bucket_kernel<<<1, 256>>>(N);
    // 3) routed GEMM1: h = gelu(x[gather] @ w1[e] + b1[e])
    mma_gemm<true><<<dim3(TILES_MAX, HDIM / 128, 1), 256>>>(
        x, 0, w1, (long long)DDIM * HDIM, b1, HDIM,
        (float*)p_hr, 0, (const int*)p_pt, (const int*)p_te, DDIM, HDIM);
    // 4) routed GEMM2: y = h @ w2[e] + b2[e]
    mma_gemm<false><<<dim3(TILES_MAX, DDIM / 128, 1), 256>>>(
        (const float*)p_hr, 0, w2, (long long)HDIM * DDIM, b2, DDIM,
        (float*)p_yb, 0, nullptr, (const int*)p_te, HDIM, DDIM);
    // 5) shared GEMM1: hs[s] = gelu(x @ sw1[s] + sb1[s])
    mma_gemm<true><<<dim3(N / 128, HDIM / 128, NSH), 256>>>(
        x, 0, sw1, (long long)DDIM * HDIM, sb1, HDIM,
        (float*)p_hs, (long long)N * HDIM, nullptr, nullptr, DDIM, HDIM);
    // 6) shared GEMM2: ys[s] = hs[s] @ sw2[s] + sb2[s]
    mma_gemm<false><<<dim3(N / 128, DDIM / 128, NSH), 256>>>(
        (const float*)p_hs, (long long)N * HDIM, sw2, (long long)HDIM * DDIM, sb2, DDIM,
        (float*)p_ys, (long long)N * DDIM, nullptr, nullptr, HDIM, DDIM);
    // 7) combine
    combine_kernel<<<(N * (DDIM / 4) + 255) / 256, 256>>>(out, N);
}

// round 10
// speedup vs baseline: 2.2228x; 1.1129x over previous
#include <cuda_runtime.h>
#include <cuda_bf16.h>
#include <math.h>
#include <stdint.h>

// Problem constants: B=4, L=2048 -> N=8192 tokens
#define NTOK 8192
#define DDIM 1024
#define HDIM 2048
#define NEXP 8
#define NSH 2
#define MAXP (2 * NTOK)
#define MAXP_PAD (MAXP + NEXP * 128)  // 17408
#define TILES_MAX (MAXP_PAD / 128)    // 136
#define MT_S (NTOK / 128)             // 64

// GEMM staging geometry (words = 32-bit packed bf16 pairs)
#define NSTG 4
#define A_STRIDE 20                    // 16 kpairs + 4 pad
#define B_STRIDE 136                   // 128 n + 8 pad
#define AH_OFF 0
#define AL_OFF 2560                    // 128*20
#define BH_OFF 5120
#define BL_OFF 7296                    // 5120 + 16*136
#define STG_W 9472                     // words per stage
#define SMEMSZ (NSTG * STG_W * 4)      // 151552 bytes

// ------------------------- scratch (__device__ globals) -------------------------
__device__ unsigned g_x_hi [(size_t)NTOK * 512];
__device__ unsigned g_x_lo [(size_t)NTOK * 512];
__device__ unsigned g_xg_hi[(size_t)MAXP_PAD * 512];
__device__ unsigned g_xg_lo[(size_t)MAXP_PAD * 512];
__device__ unsigned g_h_hi [(size_t)MAXP_PAD * 1024];
__device__ unsigned g_h_lo [(size_t)MAXP_PAD * 1024];
__device__ unsigned g_hs_hi[(size_t)NSH * NTOK * 1024];
__device__ unsigned g_hs_lo[(size_t)NSH * NTOK * 1024];
__device__ unsigned g_w1t_hi[(size_t)NEXP * 512 * HDIM];
__device__ unsigned g_w1t_lo[(size_t)NEXP * 512 * HDIM];
__device__ unsigned g_w2t_hi[(size_t)NEXP * 1024 * DDIM];
__device__ unsigned g_w2t_lo[(size_t)NEXP * 1024 * DDIM];
__device__ unsigned g_s1t_hi[(size_t)NSH * 512 * HDIM];
__device__ unsigned g_s1t_lo[(size_t)NSH * 512 * HDIM];
__device__ unsigned g_s2t_hi[(size_t)NSH * 1024 * DDIM];
__device__ unsigned g_s2t_lo[(size_t)NSH * 1024 * DDIM];
__device__ float g_ybuf[(size_t)MAXP_PAD * DDIM];
__device__ float g_ys[(size_t)NSH * NTOK * DDIM];
__device__ int   g_pair_token[MAXP_PAD];
__device__ int   g_slot_of[MAXP];
__device__ float g_gate[MAXP];
__device__ int   g_topi[MAXP];
__device__ int   g_tile_expert[TILES_MAX];

// ------------------------- helpers -------------------------
__device__ __forceinline__ uint32_t smem_u32(const void* p) {
    uint32_t a;
    asm("{ .reg .u64 t; cvta.to.shared.u64 t, %1; cvt.u32.u64 %0, t; }" : "=r"(a) : "l"(p));
    return a;
}
__device__ __forceinline__ void cp16(uint32_t dst, const void* src) {
    asm volatile("cp.async.cg.shared.global [%0], [%1], 16;" :: "r"(dst), "l"(src) : "memory");
}
#define CP_COMMIT() asm volatile("cp.async.commit_group;" ::: "memory")
#define CP_WAIT2() asm volatile("cp.async.wait_group 2;" ::: "memory")

__device__ __forceinline__ void cvt_pair(float x0, float x1, unsigned& hi, unsigned& lo) {
    __nv_bfloat16 h0 = __float2bfloat16(x0);
    __nv_bfloat16 h1 = __float2bfloat16(x1);
    float r0 = x0 - __bfloat162float(h0);
    float r1 = x1 - __bfloat162float(h1);
    __nv_bfloat16 l0 = __float2bfloat16(r0);
    __nv_bfloat16 l1 = __float2bfloat16(r1);
    hi = (unsigned)__bfloat16_as_ushort(h0) | ((unsigned)__bfloat16_as_ushort(h1) << 16);
    lo = (unsigned)__bfloat16_as_ushort(l0) | ((unsigned)__bfloat16_as_ushort(l1) << 16);
}

#define MMA_BF16(accp, a, b)                                                  \
    asm volatile(                                                             \
        "mma.sync.aligned.m16n8k16.row.col.f32.bf16.bf16.f32 "                \
        "{%0,%1,%2,%3},{%4,%5,%6,%7},{%8,%9},{%0,%1,%2,%3};"                  \
        : "+f"((accp)[0]), "+f"((accp)[1]), "+f"((accp)[2]), "+f"((accp)[3])  \
        : "r"((a)[0]), "r"((a)[1]), "r"((a)[2]), "r"((a)[3]),                 \
          "r"((b)[0]), "r"((b)[1]))

// ------------------------- router -------------------------
__global__ void router_kernel(const float* __restrict__ x, const float* __restrict__ rw,
                              const float* __restrict__ rb, int N) {
    int w = (blockIdx.x * blockDim.x + threadIdx.x) >> 5;
    int lane = threadIdx.x & 31;
    if (w >= N) return;
    const float* xr = x + (size_t)w * DDIM;
    float acc[NEXP];
#pragma unroll
    for (int e = 0; e < NEXP; e++) acc[e] = 0.f;
    for (int d = lane; d < DDIM; d += 32) {
        float xv = xr[d];
        const float* r = rw + (size_t)d * NEXP;
#pragma unroll
        for (int e = 0; e < NEXP; e++) acc[e] = fmaf(xv, r[e], acc[e]);
    }
#pragma unroll
    for (int e = 0; e < NEXP; e++)
        for (int o = 16; o > 0; o >>= 1) acc[e] += __shfl_xor_sync(0xffffffffu, acc[e], o);
    if (lane == 0) {
        float v0 = -1e30f, v1 = -1e30f;
        int i0 = 0, i1 = 0;
#pragma unroll
        for (int e = 0; e < NEXP; e++) {
            float v = acc[e] + rb[e];
            if (v > v0) { v1 = v0; i1 = i0; v0 = v; i0 = e; }
            else if (v > v1) { v1 = v; i1 = e; }
        }
        float p1 = expf(v1 - v0);
        float inv = 1.0f / (1.0f + p1);
        g_topi[2 * w] = i0; g_topi[2 * w + 1] = i1;
        g_gate[2 * w] = inv; g_gate[2 * w + 1] = p1 * inv;
    }
}

// ------------------------- bucketing -------------------------
__global__ void bucket_kernel(int N) {
    __shared__ int s_cnt[NEXP];
    __shared__ int s_off[NEXP + 1];
    __shared__ int s_c2[NEXP];
    int tid = threadIdx.x;
    if (tid < NEXP) { s_cnt[tid] = 0; s_c2[tid] = 0; }
    __syncthreads();
    int P = 2 * N;
    for (int p = tid; p < P; p += blockDim.x) atomicAdd(&s_cnt[g_topi[p]], 1);
    for (int i = tid; i < MAXP_PAD; i += blockDim.x) g_pair_token[i] = -1;
    __syncthreads();
    if (tid == 0) {
        int o = 0;
        for (int e = 0; e < NEXP; e++) { s_off[e] = o; o += ((s_cnt[e] + 127) >> 7) << 7; }
        s_off[NEXP] = o;
        int total = o >> 7;
        for (int t = 0; t < TILES_MAX; t++) {
            int ex = -1;
            if (t < total) {
                int s = t << 7;
                for (int e = 0; e < NEXP; e++)
                    if (s >= s_off[e] && s < s_off[e + 1]) ex = e;
            }
            g_tile_expert[t] = ex;
        }
    }
    __syncthreads();
    for (int p = tid; p < P; p += blockDim.x) {
        int e = g_topi[p];
        int pos = atomicAdd(&s_c2[e], 1);
        int slot = s_off[e] + pos;
        g_pair_token[slot] = p >> 1;
        g_slot_of[p] = slot;
    }
}

// ------------------------- operand pre-conversion -------------------------
// x (fp32 row-major) -> packed bf16 hi/lo words, row-major [n][D/2]
__global__ void pack_x_kernel(const float* __restrict__ x) {
    size_t idx = (size_t)blockIdx.x * blockDim.x + threadIdx.x;
    if (idx >= (size_t)NTOK * 512) return;
    float2 v = *(const float2*)(x + 2 * idx);
    unsigned h, l; cvt_pair(v.x, v.y, h, l);
    g_x_hi[idx] = h; g_x_lo[idx] = l;
}
// gathered x by slot -> [slot][D/2]
__global__ void pack_xg_kernel(const float* __restrict__ x) {
    size_t idx = (size_t)blockIdx.x * blockDim.x + threadIdx.x;
    if (idx >= (size_t)MAXP_PAD * 512) return;
    int slot = (int)(idx >> 9), w = (int)(idx & 511);
    int tok = g_pair_token[slot];
    float2 v = (tok >= 0) ? *(const float2*)(x + (size_t)tok * DDIM + 2 * w)
                          : make_float2(0.f, 0.f);
    unsigned h, l; cvt_pair(v.x, v.y, h, l);
    g_xg_hi[idx] = h; g_xg_lo[idx] = l;
}
// W [Z][K][N] fp32 -> blocks [(z*NT+nt)*KC + kc][kpair 16][n 128] packed hi/lo
__global__ void wt_kernel(const float* __restrict__ W,
                          unsigned* __restrict__ oh, unsigned* __restrict__ ol,
                          int K, int N) {
    __shared__ float t[64][33];
    int z = blockIdx.z;
    const float* Wz = W + (size_t)z * K * N;
    int k0 = blockIdx.y * 64, n0 = blockIdx.x * 32;
    int tx = threadIdx.x, ty = threadIdx.y;
#pragma unroll
    for (int i = 0; i < 8; i++) {
        int k = ty + i * 8;
        t[k][tx] = Wz[(size_t)(k0 + k) * N + n0 + tx];
    }
    __syncthreads();
    int NT = N >> 7, KC = K >> 5;
    int nl = tx;
    int nabs = n0 + nl, nt = nabs >> 7, nin = nabs & 127;
#pragma unroll
    for (int j = 0; j < 4; j++) {
        int kpl = ty + j * 8;            // 0..31
        int kabs = k0 + 2 * kpl;
        int kc = kabs >> 5, kp = kpl & 15;
        unsigned h, l; cvt_pair(t[2 * kpl][nl], t[2 * kpl + 1][nl], h, l);
        size_t d = ((size_t)(z * NT + nt) * KC + kc) * 2048 + kp * 128 + nin;
        oh[d] = h; ol[d] = l;
    }
}

// ------------------------- mma.sync GEMM with cp.async pipeline -------------------------
// 128x128 tile, BK=32 (16 kpairs), 256 threads = 8 warps (each 64x32 of C),
// bf16x3 splits (HH+HL+LH), 4-stage cp.async, one __syncthreads per k-block.
// GELU=0: C fp32 += bias. GELU=1: gelu(C+bias) -> packed bf16 hi/lo words.
template <int GELU>
__global__ void __launch_bounds__(256, 1)
mma_gemm2(const unsigned* __restrict__ Ah, const unsigned* __restrict__ Al,
          long long a_z, int a_ld,
          const unsigned* __restrict__ Bh, const unsigned* __restrict__ Bl,
          const float* __restrict__ bias_base, int bias_stride,
          float* __restrict__ Cf, long long c_z, int c_ld,
          unsigned* __restrict__ Oh, unsigned* __restrict__ Ol,
          long long o_z, int o_ld,
          const int* __restrict__ te, int nKb, int NTtot) {
    int nt = blockIdx.x, mt = blockIdx.y, z = blockIdx.z;
    int expert = te ? te[mt] : z;
    if (expert < 0) return;

    extern __shared__ unsigned smw[];
    uint32_t sb = smem_u32(smw);
    int tid = threadIdx.x, lane = tid & 31, wid = tid >> 5;
    int wm = (wid >> 2) * 64, wn = (wid & 3) * 32;
    int mBase = mt * 128;

    const unsigned* Abase_h = Ah + (size_t)z * a_z + (size_t)mBase * a_ld;
    const unsigned* Abase_l = Al + (size_t)z * a_z + (size_t)mBase * a_ld;
    const unsigned* Bbase_h = Bh + (size_t)(expert * NTtot + nt) * nKb * 2048;
    const unsigned* Bbase_l = Bl + (size_t)(expert * NTtot + nt) * nKb * 2048;

    // per-thread copy decode (8 x 16B per stage)
    int rowA = tid >> 1, c4A = (tid & 1) * 8;   // A: row t>>1, words (t&1)*8 .. +8
    int rowB = tid >> 4, cB = (tid & 15) * 8;   // B: kp = t>>4, words (t&15)*8 .. +8

    auto issue = [&](int kb) {
        uint32_t st = sb + (uint32_t)((kb & (NSTG - 1)) * STG_W) * 4;
        const unsigned* arh = Abase_h + (size_t)rowA * a_ld + kb * 16 + c4A;
        const unsigned* arl = Abase_l + (size_t)rowA * a_ld + kb * 16 + c4A;
        uint32_t da = st + (AH_OFF + rowA * A_STRIDE + c4A) * 4;
        cp16(da, arh); cp16(da + 16, arh + 4);
        uint32_t dal = st + (AL_OFF + rowA * A_STRIDE + c4A) * 4;
        cp16(dal, arl); cp16(dal + 16, arl + 4);
        const unsigned* brh = Bbase_h + (size_t)kb * 2048 + rowB * 128 + cB;
        const unsigned* brl = Bbase_l + (size_t)kb * 2048 + rowB * 128 + cB;
        uint32_t db = st + (BH_OFF + rowB * B_STRIDE + cB) * 4;
        cp16(db, brh); cp16(db + 16, brh + 4);
        uint32_t dbl = st + (BL_OFF + rowB * B_STRIDE + cB) * 4;
        cp16(dbl, brl); cp16(dbl + 16, brl + 4);
    };

    float acc[4][4][4];
#pragma unroll
    for (int a = 0; a < 4; a++)
#pragma unroll
        for (int b = 0; b < 4; b++)
#pragma unroll
            for (int c = 0; c < 4; c++) acc[a][b][c] = 0.f;

    // prologue: 3 stages in flight
#pragma unroll
    for (int s = 0; s < NSTG - 1; s++) {
        if (s < nKb) issue(s);
        CP_COMMIT();
    }

    int q = lane & 3, cm = lane >> 2;
    for (int kb = 0; kb < nKb; kb++) {
        CP_WAIT2();
        __syncthreads();
        int nx = kb + NSTG - 1;
        if (nx < nKb) issue(nx);
        CP_COMMIT();

        const unsigned* st = smw + (kb & (NSTG - 1)) * STG_W;
        const unsigned* Ahs = st + AH_OFF;
        const unsigned* Als = st + AL_OFF;
        const unsigned* Bhs = st + BH_OFF;
        const unsigned* Bls = st + BL_OFF;
#pragma unroll
        for (int ks = 0; ks < 2; ks++) {
            int r = ks * 8 + q;
            unsigned ah[4][4], al[4][4], bh[4][2], bl[4][2];
#pragma unroll
            for (int mt4 = 0; mt4 < 4; mt4++) {
                int m0 = wm + mt4 * 16 + cm;
                ah[mt4][0] = Ahs[m0 * A_STRIDE + r];
                ah[mt4][1] = Ahs[(m0 + 8) * A_STRIDE + r];
                ah[mt4][2] = Ahs[m0 * A_STRIDE + r + 4];
                ah[mt4][3] = Ahs[(m0 + 8) * A_STRIDE + r + 4];
                al[mt4][0] = Als[m0 * A_STRIDE + r];
                al[mt4][1] = Als[(m0 + 8) * A_STRIDE + r];
                al[mt4][2] = Als[m0 * A_STRIDE + r + 4];
                al[mt4][3] = Als[(m0 + 8) * A_STRIDE + r + 4];
            }
#pragma unroll
            for (int nt4 = 0; nt4 < 4; nt4++) {
                int n0 = wn + nt4 * 8 + cm;
                bh[nt4][0] = Bhs[r * B_STRIDE + n0];
                bh[nt4][1] = Bhs[(r + 4) * B_STRIDE + n0];
                bl[nt4][0] = Bls[r * B_STRIDE + n0];
                bl[nt4][1] = Bls[(r + 4) * B_STRIDE + n0];
            }
#pragma unroll
            for (int mt4 = 0; mt4 < 4; mt4++)
#pragma unroll
                for (int nt4 = 0; nt4 < 4; nt4++)
                    MMA_BF16(acc[mt4][nt4], ah[mt4], bh[nt4]);
#pragma unroll
            for (int mt4 = 0; mt4 < 4; mt4++)
#pragma unroll
                for (int nt4 = 0; nt4 < 4; nt4++)
                    MMA_BF16(acc[mt4][nt4], ah[mt4], bl[nt4]);
#pragma unroll
            for (int mt4 = 0; mt4 < 4; mt4++)
#pragma unroll
                for (int nt4 = 0; nt4 < 4; nt4++)
                    MMA_BF16(acc[mt4][nt4], al[mt4], bh[nt4]);
        }
    }

    // epilogue
    const float* bias = bias_base + (size_t)expert * bias_stride + nt * 128;
#pragma unroll
    for (int mt4 = 0; mt4 < 4; mt4++) {
#pragma unroll
        for (int nt4 = 0; nt4 < 4; nt4++) {
            int row0 = mBase + wm + mt4 * 16 + (lane >> 2);
            int c0 = wn + nt4 * 8 + (lane & 3) * 2;
            float b0 = bias[c0], b1 = bias[c0 + 1];
            float v0 = acc[mt4][nt4][0] + b0;
            float v1 = acc[mt4][nt4][1] + b1;
            float v2 = acc[mt4][nt4][2] + b0;
            float v3 = acc[mt4][nt4][3] + b1;
            if (GELU) {
                v0 = 0.5f * v0 * (1.0f + erff(v0 * 0.70710678118654752f));
                v1 = 0.5f * v1 * (1.0f + erff(v1 * 0.70710678118654752f));
                v2 = 0.5f * v2 * (1.0f + erff(v2 * 0.70710678118654752f));
                v3 = 0.5f * v3 * (1.0f + erff(v3 * 0.70710678118654752f));
                unsigned h0, l0, h1, l1;
                cvt_pair(v0, v1, h0, l0);
                cvt_pair(v2, v3, h1, l1);
                size_t w = (size_t)((nt * 128 + c0) >> 1);
                size_t b0i = (size_t)z * o_z + (size_t)row0 * o_ld + w;
                size_t b1i = b0i + (size_t)8 * o_ld;
                Oh[b0i] = h0; Ol[b0i] = l0;
                Oh[b1i] = h1; Ol[b1i] = l1;
            } else {
                size_t base = (size_t)z * c_z + (size_t)row0 * c_ld + nt * 128 + c0;
                *(float2*)&Cf[base] = make_float2(v0, v1);
                *(float2*)&Cf[base + (size_t)8 * c_ld] = make_float2(v2, v3);
            }
        }
    }
}

// ------------------------- final combine -------------------------
__global__ void combine_kernel(float* __restrict__ out, int N) {
    int idx = blockIdx.x * blockDim.x + threadIdx.x;
    int total = N * (DDIM / 4);
    if (idx >= total) return;
    int n = idx / (DDIM / 4);
    int d = (idx % (DDIM / 4)) * 4;
    const float4 s0 = *(const float4*)&g_ys[(size_t)n * DDIM + d];
    const float4 s1 = *(const float4*)&g_ys[(size_t)N * DDIM + (size_t)n * DDIM + d];
    int sl0 = g_slot_of[2 * n], sl1 = g_slot_of[2 * n + 1];
    float w0 = g_gate[2 * n], w1 = g_gate[2 * n + 1];
    const float4 y0 = *(const float4*)&g_ybuf[(size_t)sl0 * DDIM + d];
    const float4 y1 = *(const float4*)&g_ybuf[(size_t)sl1 * DDIM + d];
    const float inv_s = 1.0f / NSH;
    float4 o;
    o.x = inv_s * (s0.x + s1.x) + w0 * y0.x + w1 * y1.x;
    o.y = inv_s * (s0.y + s1.y) + w0 * y0.y + w1 * y1.y;
    o.z = inv_s * (s0.z + s1.z) + w0 * y0.z + w1 * y1.z;
    o.w = inv_s * (s0.w + s1.w) + w0 * y0.w + w1 * y1.w;
    *(float4*)&out[(size_t)n * DDIM + d] = o;
}

// ------------------------- launch -------------------------
#define SYM(p, s) void* p; cudaGetSymbolAddress(&p, s)

extern "C" void kernel_launch(void* const* d_in, const int* in_sizes, int n_in,
                              void* d_out, int out_size) {
    const float* x   = (const float*)d_in[0];
    const float* rw  = (const float*)d_in[1];
    const float* rb  = (const float*)d_in[2];
    const float* w1  = (const float*)d_in[3];
    const float* b1  = (const float*)d_in[4];
    const float* w2  = (const float*)d_in[5];
    const float* b2  = (const float*)d_in[6];
    const float* sw1 = (const float*)d_in[7];
    const float* sb1 = (const float*)d_in[8];
    const float* sw2 = (const float*)d_in[9];
    const float* sb2 = (const float*)d_in[10];
    float* out = (float*)d_out;
    int N = in_sizes[0] / DDIM;

    cudaFuncSetAttribute(mma_gemm2<0>, cudaFuncAttributeMaxDynamicSharedMemorySize, SMEMSZ);
    cudaFuncSetAttribute(mma_gemm2<1>, cudaFuncAttributeMaxDynamicSharedMemorySize, SMEMSZ);

    SYM(p_xh, g_x_hi);    SYM(p_xl, g_x_lo);
    SYM(p_gh, g_xg_hi);   SYM(p_gl, g_xg_lo);
    SYM(p_hh, g_h_hi);    SYM(p_hl, g_h_lo);
    SYM(p_sh, g_hs_hi);   SYM(p_sl, g_hs_lo);
    SYM(p_w1h, g_w1t_hi); SYM(p_w1l, g_w1t_lo);
    SYM(p_w2h, g_w2t_hi); SYM(p_w2l, g_w2t_lo);
    SYM(p_s1h, g_s1t_hi); SYM(p_s1l, g_s1t_lo);
    SYM(p_s2h, g_s2t_hi); SYM(p_s2l, g_s2t_lo);
    SYM(p_yb, g_ybuf);    SYM(p_ys, g_ys);
    SYM(p_te, g_tile_expert);

    // 1) router + bucketing
    router_kernel<<<(N + 7) / 8, 256>>>(x, rw, rb, N);
    bucket_kernel<<<1, 256>>>(N);
    // 2) operand pre-conversion
    pack_x_kernel<<<(NTOK * 512 + 255) / 256, 256>>>(x);
    pack_xg_kernel<<<(MAXP_PAD * 512 + 255) / 256, 256>>>(x);
    dim3 tb(32, 8);
    wt_kernel<<<dim3(HDIM / 32, DDIM / 64, NEXP), tb>>>(w1, (unsigned*)p_w1h, (unsigned*)p_w1l, DDIM, HDIM);
    wt_kernel<<<dim3(DDIM / 32, HDIM / 64, NEXP), tb>>>(w2, (unsigned*)p_w2h, (unsigned*)p_w2l, HDIM, DDIM);
    wt_kernel<<<dim3(HDIM / 32, DDIM / 64, NSH), tb>>>(sw1, (unsigned*)p_s1h, (unsigned*)p_s1l, DDIM, HDIM);
    wt_kernel<<<dim3(DDIM / 32, HDIM / 64, NSH), tb>>>(sw2, (unsigned*)p_s2h, (unsigned*)p_s2l, HDIM, DDIM);
    // 3) routed GEMM1: h = gelu(xg @ w1[e] + b1[e]) -> packed bf16
    mma_gemm2<1><<<dim3(HDIM / 128, TILES_MAX, 1), 256, SMEMSZ>>>(
        (unsigned*)p_gh, (unsigned*)p_gl, 0, 512,
        (unsigned*)p_w1h, (unsigned*)p_w1l, b1, HDIM,
        nullptr, 0, 0, (unsigned*)p_hh, (unsigned*)p_hl, 0, 1024,
        (const int*)p_te, DDIM / 32, HDIM / 128);
    // 4) routed GEMM2: y = h @ w2[e] + b2[e] -> fp32
    mma_gemm2<0><<<dim3(DDIM / 128, TILES_MAX, 1), 256, SMEMSZ>>>(
        (unsigned*)p_hh, (unsigned*)p_hl, 0, 1024,
        (unsigned*)p_w2h, (unsigned*)p_w2l, b2, DDIM,
        (float*)p_yb, 0, DDIM, nullptr, nullptr, 0, 0,
        (const int*)p_te, HDIM / 32, DDIM / 128);
    // 5) shared GEMM1: hs[s] = gelu(x @ sw1[s] + sb1[s]) -> packed bf16
    //    NOTE: A (x) is the SAME for both shared experts -> a_z stride MUST be 0.
    mma_gemm2<1><<<dim3(HDIM / 128, MT_S, NSH), 256, SMEMSZ>>>(
        (unsigned*)p_xh, (unsigned*)p_xl, 0, 512,
        (unsigned*)p_s1h, (unsigned*)p_s1l, sb1, HDIM,
        nullptr, 0, 0, (unsigned*)p_sh, (unsigned*)p_sl, (long long)NTOK * 1024, 1024,
        nullptr, DDIM / 32, HDIM / 128);
    // 6) shared GEMM2: ys[s] = hs[s] @ sw2[s] + sb2[s] -> fp32
    mma_gemm2<0><<<dim3(DDIM / 128, MT_S, NSH), 256, SMEMSZ>>>(
        (unsigned*)p_sh, (unsigned*)p_sl, (long long)NTOK * 1024, 1024,
        (unsigned*)p_s2h, (unsigned*)p_s2l, sb2, DDIM,
        (float*)p_ys, (long long)NTOK * DDIM, DDIM, nullptr, nullptr, 0, 0,
        nullptr, HDIM / 32, DDIM / 128);
    // 7) combine
    combine_kernel<<<(N * (DDIM / 4) + 255) / 256, 256>>>(out, N);
}